// round 1
// baseline (speedup 1.0000x reference)
#include <cuda_runtime.h>
#include <math.h>

#define B_  4
#define S_  2048
#define D_  1024
#define H_  16
#define DH_ 64
#define M_  (B_*S_)   // 8192

// Scratch (module-load allocations, allowed)
__device__ float g_Q [B_*H_*S_*DH_];   // [B,H,S,DH]
__device__ float g_Kt[B_*H_*DH_*S_];   // [B,H,DH,S]  (K transposed)
__device__ float g_V [B_*H_*S_*DH_];   // [B,H,S,DH]
__device__ float g_C [B_*S_*D_];       // [B,S,D] concat(ctx)

// ---------------------------------------------------------------------------
// Kernel 1: fused QKV projection.  X[8192,1024] @ W_h[1024,64] per (matrix, head)
// grid = (64 m-tiles, 48 n-tiles: nt>>4 = {Q,K,V}, nt&15 = head)
// ---------------------------------------------------------------------------
__global__ __launch_bounds__(256) void qkv_kernel(
    const float* __restrict__ x,
    const float* __restrict__ Wq, const float* __restrict__ bq,
    const float* __restrict__ Wk, const float* __restrict__ bk,
    const float* __restrict__ Wv, const float* __restrict__ bv)
{
    __shared__ float As[16][132];   // A^T tile, padded (2-way max conflict on store)
    __shared__ float Bs[16][64];

    const int mt  = blockIdx.x;
    const int nt  = blockIdx.y;
    const int qkv = nt >> 4;
    const int h   = nt & 15;

    const float* W;
    const float* bias;
    if (qkv == 0)      { W = Wq; bias = bq; }
    else if (qkv == 1) { W = Wk; bias = bk; }
    else               { W = Wv; bias = bv; }
    W    += h * (D_ * DH_);
    bias += h * DH_;

    const int tid = threadIdx.x;
    const int ty = tid >> 4, tx = tid & 15;
    const int m0 = mt * 128;

    float acc[8][4];
    #pragma unroll
    for (int i = 0; i < 8; i++)
        #pragma unroll
        for (int j = 0; j < 4; j++) acc[i][j] = 0.f;

    for (int k0 = 0; k0 < D_; k0 += 16) {
        #pragma unroll
        for (int t = 0; t < 2; t++) {
            int i  = tid + t * 256;
            int mm = i >> 2;
            int kg = (i & 3) << 2;
            float4 a = *(const float4*)&x[(m0 + mm) * D_ + k0 + kg];
            As[kg + 0][mm] = a.x; As[kg + 1][mm] = a.y;
            As[kg + 2][mm] = a.z; As[kg + 3][mm] = a.w;
        }
        {
            int kr = tid >> 4, c4 = (tid & 15) << 2;
            *(float4*)&Bs[kr][c4] = *(const float4*)&W[(k0 + kr) * DH_ + c4];
        }
        __syncthreads();
        #pragma unroll
        for (int k = 0; k < 16; k++) {
            float4 a0 = *(const float4*)&As[k][ty * 8];
            float4 a1 = *(const float4*)&As[k][ty * 8 + 4];
            float4 b4 = *(const float4*)&Bs[k][tx * 4];
            float av[8] = {a0.x, a0.y, a0.z, a0.w, a1.x, a1.y, a1.z, a1.w};
            float bf[4] = {b4.x, b4.y, b4.z, b4.w};
            #pragma unroll
            for (int i = 0; i < 8; i++)
                #pragma unroll
                for (int j = 0; j < 4; j++)
                    acc[i][j] = fmaf(av[i], bf[j], acc[i][j]);
        }
        __syncthreads();
    }

    const int e0 = tx * 4;
    float4 bias4 = *(const float4*)&bias[e0];
    #pragma unroll
    for (int i = 0; i < 8; i++) {
        int mrow = m0 + ty * 8 + i;
        int bi = mrow >> 11;         // batch
        int si = mrow & 2047;        // seq pos
        int bh = bi * H_ + h;
        float r0 = acc[i][0] + bias4.x;
        float r1 = acc[i][1] + bias4.y;
        float r2 = acc[i][2] + bias4.z;
        float r3 = acc[i][3] + bias4.w;
        if (qkv == 1) {
            // transposed store: g_Kt[bh][e][s]
            int base = (bh * DH_) * S_ + si;
            g_Kt[base + (e0 + 0) * S_] = r0;
            g_Kt[base + (e0 + 1) * S_] = r1;
            g_Kt[base + (e0 + 2) * S_] = r2;
            g_Kt[base + (e0 + 3) * S_] = r3;
        } else {
            float* dst = (qkv == 0) ? g_Q : g_V;
            *(float4*)&dst[(bh * S_ + si) * DH_ + e0] = make_float4(r0, r1, r2, r3);
        }
    }
}

// ---------------------------------------------------------------------------
// Kernel 2: flash attention. Block = (q-tile of 128 rows, head, batch).
// 256 threads: ty=tid/16 -> 8 q rows each, tx=tid%16 -> 4 dh cols each.
// ---------------------------------------------------------------------------
__device__ __forceinline__ float grp16_max(float v) {
    v = fmaxf(v, __shfl_xor_sync(0xffffffffu, v, 8));
    v = fmaxf(v, __shfl_xor_sync(0xffffffffu, v, 4));
    v = fmaxf(v, __shfl_xor_sync(0xffffffffu, v, 2));
    v = fmaxf(v, __shfl_xor_sync(0xffffffffu, v, 1));
    return v;
}
__device__ __forceinline__ float grp16_sum(float v) {
    v += __shfl_xor_sync(0xffffffffu, v, 8);
    v += __shfl_xor_sync(0xffffffffu, v, 4);
    v += __shfl_xor_sync(0xffffffffu, v, 2);
    v += __shfl_xor_sync(0xffffffffu, v, 1);
    return v;
}

__global__ __launch_bounds__(256) void attn_kernel()
{
    extern __shared__ float sm[];
    float* Qs  = sm;                 // 128*64 = 8192 floats
    float* KTs = sm + 8192;          //  64*64 = 4096
    float* Vs  = sm + 12288;         //  64*64 = 4096
    float* Ps  = sm + 16384;         // 128*64 = 8192
    // total 24576 floats = 96 KB dynamic smem

    const int tid = threadIdx.x;
    const int ty = tid >> 4, tx = tid & 15;
    const int qt = blockIdx.x;      // 0..15
    const int h  = blockIdx.y;
    const int b  = blockIdx.z;
    const int bh = b * H_ + h;
    const int q0 = qt * 128;
    const int qr0 = ty * 8;

    // Load Q tile, fold in 1/sqrt(DH) = 0.125
    const float* Qg = g_Q + (bh * S_ + q0) * DH_;
    #pragma unroll
    for (int t = 0; t < 8; t++) {
        int i = tid + t * 256;
        int r = i >> 4, c4 = (i & 15) << 2;
        float4 v = *(const float4*)&Qg[r * DH_ + c4];
        v.x *= 0.125f; v.y *= 0.125f; v.z *= 0.125f; v.w *= 0.125f;
        *(float4*)&Qs[r * 64 + c4] = v;
    }

    float o[8][4];
    float mrow[8], lrow[8];
    #pragma unroll
    for (int i = 0; i < 8; i++) {
        mrow[i] = -1e30f; lrow[i] = 0.f;
        #pragma unroll
        for (int j = 0; j < 4; j++) o[i][j] = 0.f;
    }

    const float* Kg = g_Kt + bh * DH_ * S_;
    const float* Vg = g_V  + bh * S_ * DH_;

    for (int kt0 = 0; kt0 < S_; kt0 += 64) {
        __syncthreads();   // prior O-update (reads Vs/Ps) complete
        #pragma unroll
        for (int t = 0; t < 4; t++) {
            int i = tid + t * 256;
            int r = i >> 4, c4 = (i & 15) << 2;
            *(float4*)&KTs[r * 64 + c4] = *(const float4*)&Kg[r * S_ + kt0 + c4];
            *(float4*)&Vs [r * 64 + c4] = *(const float4*)&Vg[(kt0 + r) * DH_ + c4];
        }
        __syncthreads();

        // S = (Q*scale) @ K^T : s[i][j], rows qr0+i, key cols kt0 + tx*4+j
        float s[8][4];
        #pragma unroll
        for (int i = 0; i < 8; i++)
            #pragma unroll
            for (int j = 0; j < 4; j++) s[i][j] = 0.f;

        #pragma unroll 4
        for (int d4 = 0; d4 < 16; d4++) {
            float kv[4][4];
            #pragma unroll
            for (int dd = 0; dd < 4; dd++) {
                float4 t4 = *(const float4*)&KTs[(d4 * 4 + dd) * 64 + tx * 4];
                kv[dd][0] = t4.x; kv[dd][1] = t4.y; kv[dd][2] = t4.z; kv[dd][3] = t4.w;
            }
            #pragma unroll
            for (int i = 0; i < 8; i++) {
                float4 q4 = *(const float4*)&Qs[(qr0 + i) * 64 + d4 * 4];
                float qv[4] = {q4.x, q4.y, q4.z, q4.w};
                #pragma unroll
                for (int dd = 0; dd < 4; dd++)
                    #pragma unroll
                    for (int j = 0; j < 4; j++)
                        s[i][j] = fmaf(qv[dd], kv[dd][j], s[i][j]);
            }
        }

        // Online softmax; write P tile
        #pragma unroll
        for (int i = 0; i < 8; i++) {
            float rm = fmaxf(fmaxf(s[i][0], s[i][1]), fmaxf(s[i][2], s[i][3]));
            rm = grp16_max(rm);
            float mn = fmaxf(mrow[i], rm);
            float corr = __expf(mrow[i] - mn);
            float ps = 0.f;
            #pragma unroll
            for (int j = 0; j < 4; j++) { s[i][j] = __expf(s[i][j] - mn); ps += s[i][j]; }
            ps = grp16_sum(ps);
            lrow[i] = lrow[i] * corr + ps;
            mrow[i] = mn;
            #pragma unroll
            for (int j = 0; j < 4; j++) o[i][j] *= corr;
            *(float4*)&Ps[(qr0 + i) * 64 + tx * 4] =
                make_float4(s[i][0], s[i][1], s[i][2], s[i][3]);
        }
        __syncthreads();

        // O += P @ V
        #pragma unroll 4
        for (int k4 = 0; k4 < 16; k4++) {
            float vv[4][4];
            #pragma unroll
            for (int kk = 0; kk < 4; kk++) {
                float4 t4 = *(const float4*)&Vs[(k4 * 4 + kk) * 64 + tx * 4];
                vv[kk][0] = t4.x; vv[kk][1] = t4.y; vv[kk][2] = t4.z; vv[kk][3] = t4.w;
            }
            #pragma unroll
            for (int i = 0; i < 8; i++) {
                float4 p4 = *(const float4*)&Ps[(qr0 + i) * 64 + k4 * 4];
                float pv[4] = {p4.x, p4.y, p4.z, p4.w};
                #pragma unroll
                for (int kk = 0; kk < 4; kk++)
                    #pragma unroll
                    for (int j = 0; j < 4; j++)
                        o[i][j] = fmaf(pv[kk], vv[kk][j], o[i][j]);
            }
        }
    }

    // Normalize and write ctx into concat layout [B,S,H*DH]
    float* Cg = g_C + (b * S_ + q0) * D_ + h * DH_;
    #pragma unroll
    for (int i = 0; i < 8; i++) {
        float inv = 1.f / lrow[i];
        *(float4*)&Cg[(qr0 + i) * D_ + tx * 4] =
            make_float4(o[i][0] * inv, o[i][1] * inv, o[i][2] * inv, o[i][3] * inv);
    }
}

// ---------------------------------------------------------------------------
// Kernel 3: output projection. g_C[8192,1024] @ Wo[1024,1024] + bo -> out
// grid = (64 m-tiles, 16 n-tiles)
// ---------------------------------------------------------------------------
__global__ __launch_bounds__(256) void proj_kernel(
    const float* __restrict__ Wo, const float* __restrict__ bo,
    float* __restrict__ out)
{
    __shared__ float As[16][132];
    __shared__ float Bs[16][64];

    const int mt = blockIdx.x, nt = blockIdx.y;
    const int tid = threadIdx.x;
    const int ty = tid >> 4, tx = tid & 15;
    const int m0 = mt * 128, n0 = nt * 64;

    float acc[8][4];
    #pragma unroll
    for (int i = 0; i < 8; i++)
        #pragma unroll
        for (int j = 0; j < 4; j++) acc[i][j] = 0.f;

    for (int k0 = 0; k0 < D_; k0 += 16) {
        #pragma unroll
        for (int t = 0; t < 2; t++) {
            int i  = tid + t * 256;
            int mm = i >> 2;
            int kg = (i & 3) << 2;
            float4 a = *(const float4*)&g_C[(m0 + mm) * D_ + k0 + kg];
            As[kg + 0][mm] = a.x; As[kg + 1][mm] = a.y;
            As[kg + 2][mm] = a.z; As[kg + 3][mm] = a.w;
        }
        {
            int kr = tid >> 4, c4 = (tid & 15) << 2;
            *(float4*)&Bs[kr][c4] = *(const float4*)&Wo[(k0 + kr) * D_ + n0 + c4];
        }
        __syncthreads();
        #pragma unroll
        for (int k = 0; k < 16; k++) {
            float4 a0 = *(const float4*)&As[k][ty * 8];
            float4 a1 = *(const float4*)&As[k][ty * 8 + 4];
            float4 b4 = *(const float4*)&Bs[k][tx * 4];
            float av[8] = {a0.x, a0.y, a0.z, a0.w, a1.x, a1.y, a1.z, a1.w};
            float bf[4] = {b4.x, b4.y, b4.z, b4.w};
            #pragma unroll
            for (int i = 0; i < 8; i++)
                #pragma unroll
                for (int j = 0; j < 4; j++)
                    acc[i][j] = fmaf(av[i], bf[j], acc[i][j]);
        }
        __syncthreads();
    }

    float4 bias4 = *(const float4*)&bo[n0 + tx * 4];
    #pragma unroll
    for (int i = 0; i < 8; i++) {
        int mrow = m0 + ty * 8 + i;
        *(float4*)&out[mrow * D_ + n0 + tx * 4] =
            make_float4(acc[i][0] + bias4.x, acc[i][1] + bias4.y,
                        acc[i][2] + bias4.z, acc[i][3] + bias4.w);
    }
}

// ---------------------------------------------------------------------------
extern "C" void kernel_launch(void* const* d_in, const int* in_sizes, int n_in,
                              void* d_out, int out_size)
{
    const float* x  = (const float*)d_in[0];
    const float* Wq = (const float*)d_in[1];
    const float* bq = (const float*)d_in[2];
    const float* Wk = (const float*)d_in[3];
    const float* bk = (const float*)d_in[4];
    const float* Wv = (const float*)d_in[5];
    const float* bv = (const float*)d_in[6];
    const float* Wo = (const float*)d_in[7];
    const float* bo = (const float*)d_in[8];
    float* out = (float*)d_out;

    cudaFuncSetAttribute(attn_kernel,
                         cudaFuncAttributeMaxDynamicSharedMemorySize, 96 * 1024);

    qkv_kernel<<<dim3(64, 48), 256>>>(x, Wq, bq, Wk, bk, Wv, bv);
    attn_kernel<<<dim3(16, 16, 4), 256, 96 * 1024>>>();
    proj_kernel<<<dim3(64, 16), 256>>>(Wo, bo, out);
}

// round 3
// speedup vs baseline: 3.0234x; 3.0234x over previous
#include <cuda_runtime.h>
#include <cstdint>
#include <math.h>

#define B_  4
#define S_  2048
#define D_  1024
#define H_  16
#define DH_ 64

// ---------------------------------------------------------------------------
// Scratch (__device__ globals; no runtime allocation allowed)
// ---------------------------------------------------------------------------
__device__ float g_X  [B_*S_*D_];          // tf32-rounded x
__device__ float g_Q  [B_*H_*S_*DH_];      // [B,H,S,DH]  (pre-scaled by 0.125, rounded)
__device__ float g_K  [B_*H_*S_*DH_];      // [B,H,S,DH]  (rounded)
__device__ float g_V  [B_*H_*S_*DH_];      // [B,H,S,DH]  (rounded)
__device__ float g_C  [B_*S_*D_];          // [B,S,D] concat ctx (rounded)
__device__ float g_Wt [48*DH_*D_];         // [(h*3+m)*64 + e][d]  (rounded)
__device__ float g_WoT[D_*D_];             // [n][k] = Wo[k][n]    (rounded)

// ---------------------------------------------------------------------------
// Helpers
// ---------------------------------------------------------------------------
__device__ __forceinline__ uint32_t smem_u32(const void* p) {
    uint32_t a;
    asm("{ .reg .u64 t; cvta.to.shared.u64 t, %1; cvt.u32.u64 %0, t; }" : "=r"(a) : "l"(p));
    return a;
}
__device__ __forceinline__ float rna(float f) {
    uint32_t u;
    asm("cvt.rna.tf32.f32 %0, %1;" : "=r"(u) : "f"(f));
    return __uint_as_float(u);
}
__device__ __forceinline__ void cp16(uint32_t sa, const void* g) {
    asm volatile("cp.async.cg.shared.global [%0], [%1], 16;" :: "r"(sa), "l"(g));
}
#define CP_COMMIT() asm volatile("cp.async.commit_group;" ::: "memory")
#define CP_WAIT(n)  asm volatile("cp.async.wait_group %0;" :: "n"(n) : "memory")

// D(16x8) += A(16x8) * B(8x8), tf32 inputs, f32 accum.
// Layouts (lane: g = lane>>2, t = lane&3):
//  a0=(g,t) a1=(g+8,t) a2=(g,t+4) a3=(g+8,t+4)
//  b0=(k=t,n=g) b1=(k=t+4,n=g)
//  c0=(g,2t) c1=(g,2t+1) c2=(g+8,2t) c3=(g+8,2t+1)
__device__ __forceinline__ void mma8(float* c, uint32_t a0, uint32_t a1, uint32_t a2,
                                     uint32_t a3, uint32_t b0, uint32_t b1) {
    asm volatile(
        "mma.sync.aligned.m16n8k8.row.col.f32.tf32.tf32.f32 "
        "{%0,%1,%2,%3}, {%4,%5,%6,%7}, {%8,%9}, {%0,%1,%2,%3};"
        : "+f"(c[0]), "+f"(c[1]), "+f"(c[2]), "+f"(c[3])
        : "r"(a0), "r"(a1), "r"(a2), "r"(a3), "r"(b0), "r"(b1));
}
__device__ __forceinline__ uint32_t fu(float f) { return __float_as_uint(f); }

// ---------------------------------------------------------------------------
// Prep kernels (tf32 rounding + weight transposes)
// ---------------------------------------------------------------------------
__global__ __launch_bounds__(256) void cvt_x_kernel(const float* __restrict__ x)
{
    int i = (blockIdx.x * 256 + threadIdx.x) * 4;
    float4 v = *(const float4*)&x[i];
    v.x = rna(v.x); v.y = rna(v.y); v.z = rna(v.z); v.w = rna(v.w);
    *(float4*)&g_X[i] = v;
}

__global__ __launch_bounds__(256) void transpose_qkv_kernel(
    const float* __restrict__ Wq, const float* __restrict__ Wk, const float* __restrict__ Wv)
{
    __shared__ float t[32][33];
    int z = blockIdx.z;            // 0..47 = h*3 + mtx
    int h = z / 3, mtx = z % 3;
    const float* W = (mtx == 0 ? Wq : (mtx == 1 ? Wk : Wv)) + h * D_ * DH_;
    float* out = g_Wt + (size_t)z * DH_ * D_;
    int d0 = blockIdx.x * 32, e0 = blockIdx.y * 32;
    int tx = threadIdx.x & 31, ty = threadIdx.x >> 5;
    #pragma unroll
    for (int i = 0; i < 4; i++)
        t[ty + 8 * i][tx] = W[(d0 + ty + 8 * i) * DH_ + e0 + tx];
    __syncthreads();
    #pragma unroll
    for (int i = 0; i < 4; i++)
        out[(e0 + ty + 8 * i) * D_ + d0 + tx] = rna(t[tx][ty + 8 * i]);
}

__global__ __launch_bounds__(256) void transpose_wo_kernel(const float* __restrict__ Wo)
{
    __shared__ float t[32][33];
    int d0 = blockIdx.x * 32, n0 = blockIdx.y * 32;
    int tx = threadIdx.x & 31, ty = threadIdx.x >> 5;
    #pragma unroll
    for (int i = 0; i < 4; i++)
        t[ty + 8 * i][tx] = Wo[(d0 + ty + 8 * i) * D_ + n0 + tx];
    __syncthreads();
    #pragma unroll
    for (int i = 0; i < 4; i++)
        g_WoT[(n0 + ty + 8 * i) * D_ + d0 + tx] = rna(t[tx][ty + 8 * i]);
}

// ---------------------------------------------------------------------------
// Shared GEMM mainloop: C[128,64] = A[128,1024] @ B[64,1024]^T
// 256 threads, warps 4(m) x 2(n), warp tile 32x32.
// smem: As 2x[128][36], Bs 2x[64][36]  (13824 floats = 55296 B)
// ---------------------------------------------------------------------------
#define AS_STRIDE 36
#define AS_BUF (128*36)
#define BS_BUF (64*36)
#define GEMM_SMEM ((2*AS_BUF + 2*BS_BUF) * 4)

__device__ __forceinline__ void gemm_stage(const float* __restrict__ Ag,
                                           const float* __restrict__ Bg,
                                           uint32_t as_b, uint32_t bs_b,
                                           int k0, int buf, int tid)
{
    uint32_t ab = as_b + buf * (AS_BUF * 4);
    #pragma unroll
    for (int t = 0; t < 4; t++) {
        int idx = tid + t * 256;
        int r = idx >> 3, c4 = (idx & 7) * 4;
        cp16(ab + (r * AS_STRIDE + c4) * 4, Ag + (size_t)r * D_ + k0 + c4);
    }
    uint32_t bb = bs_b + buf * (BS_BUF * 4);
    #pragma unroll
    for (int t = 0; t < 2; t++) {
        int idx = tid + t * 256;
        int r = idx >> 3, c4 = (idx & 7) * 4;
        cp16(bb + (r * AS_STRIDE + c4) * 4, Bg + (size_t)r * D_ + k0 + c4);
    }
}

__device__ __forceinline__ void gemm_mainloop(const float* __restrict__ Ag,
                                              const float* __restrict__ Bg,
                                              float c[2][4][4], float* sm)
{
    float* As = sm;
    float* Bs = sm + 2 * AS_BUF;
    const int tid = threadIdx.x;
    const int wid = tid >> 5, lane = tid & 31;
    const int g = lane >> 2, tg = lane & 3;
    const int wm = wid >> 1, wn = wid & 1;
    uint32_t as_b = smem_u32(As), bs_b = smem_u32(Bs);

    #pragma unroll
    for (int i = 0; i < 2; i++)
        #pragma unroll
        for (int j = 0; j < 4; j++)
            #pragma unroll
            for (int q = 0; q < 4; q++) c[i][j][q] = 0.f;

    gemm_stage(Ag, Bg, as_b, bs_b, 0, 0, tid);
    CP_COMMIT();

    for (int s = 0; s < 32; s++) {
        int p = s & 1;
        if (s + 1 < 32) {
            __syncthreads();                       // prev compute done with buf !p
            gemm_stage(Ag, Bg, as_b, bs_b, (s + 1) * 32, !p, tid);
            CP_COMMIT();
            CP_WAIT(1);
        } else {
            CP_WAIT(0);
        }
        __syncthreads();

        const float* Ab = As + p * AS_BUF;
        const float* Bb = Bs + p * BS_BUF;
        #pragma unroll
        for (int ks = 0; ks < 4; ks++) {
            uint32_t a[2][4], b[4][2];
            #pragma unroll
            for (int sub = 0; sub < 2; sub++) {
                int r = wm * 32 + sub * 16 + g;
                int col = ks * 8 + tg;
                a[sub][0] = fu(Ab[r * AS_STRIDE + col]);
                a[sub][1] = fu(Ab[(r + 8) * AS_STRIDE + col]);
                a[sub][2] = fu(Ab[r * AS_STRIDE + col + 4]);
                a[sub][3] = fu(Ab[(r + 8) * AS_STRIDE + col + 4]);
            }
            #pragma unroll
            for (int nt = 0; nt < 4; nt++) {
                int r = wn * 32 + nt * 8 + g;
                int col = ks * 8 + tg;
                b[nt][0] = fu(Bb[r * AS_STRIDE + col]);
                b[nt][1] = fu(Bb[r * AS_STRIDE + col + 4]);
            }
            #pragma unroll
            for (int sub = 0; sub < 2; sub++)
                #pragma unroll
                for (int nt = 0; nt < 4; nt++)
                    mma8(c[sub][nt], a[sub][0], a[sub][1], a[sub][2], a[sub][3],
                         b[nt][0], b[nt][1]);
        }
    }
}

// ---------------------------------------------------------------------------
// QKV GEMM: grid (64 m-tiles, 48 z = h*3+mtx)
// ---------------------------------------------------------------------------
__global__ __launch_bounds__(256) void qkv_gemm_kernel(
    const float* __restrict__ bq, const float* __restrict__ bk,
    const float* __restrict__ bv)
{
    extern __shared__ float sm[];
    const int mt = blockIdx.x, z = blockIdx.y;
    const int h = z / 3, mtx = z % 3;
    float c[2][4][4];
    gemm_mainloop(g_X + (size_t)mt * 128 * D_, g_Wt + (size_t)z * DH_ * D_, c, sm);

    const int tid = threadIdx.x;
    const int wid = tid >> 5, lane = tid & 31;
    const int g = lane >> 2, tg = lane & 3;
    const int wm = wid >> 1, wn = wid & 1;
    const float* bias = (mtx == 0 ? bq : (mtx == 1 ? bk : bv)) + h * DH_;
    float* dst = (mtx == 0 ? g_Q : (mtx == 1 ? g_K : g_V));
    const float scale = (mtx == 0) ? 0.125f : 1.0f;

    #pragma unroll
    for (int sub = 0; sub < 2; sub++) {
        #pragma unroll
        for (int half = 0; half < 2; half++) {
            int m = mt * 128 + wm * 32 + sub * 16 + g + half * 8;
            int bi = m >> 11, si = m & 2047;
            float* row = dst + ((size_t)(bi * H_ + h) * S_ + si) * DH_;
            #pragma unroll
            for (int nt = 0; nt < 4; nt++) {
                int e = wn * 32 + nt * 8 + 2 * tg;
                float v0 = rna((c[sub][nt][half * 2 + 0] + bias[e]) * scale);
                float v1 = rna((c[sub][nt][half * 2 + 1] + bias[e + 1]) * scale);
                *(float2*)&row[e] = make_float2(v0, v1);
            }
        }
    }
}

// ---------------------------------------------------------------------------
// Output projection GEMM: grid (64 m-tiles, 16 n-tiles)
// ---------------------------------------------------------------------------
__global__ __launch_bounds__(256) void proj_gemm_kernel(
    const float* __restrict__ bo, float* __restrict__ out)
{
    extern __shared__ float sm[];
    const int mt = blockIdx.x, nt0 = blockIdx.y;
    float c[2][4][4];
    gemm_mainloop(g_C + (size_t)mt * 128 * D_, g_WoT + (size_t)nt0 * 64 * D_, c, sm);

    const int tid = threadIdx.x;
    const int wid = tid >> 5, lane = tid & 31;
    const int g = lane >> 2, tg = lane & 3;
    const int wm = wid >> 1, wn = wid & 1;

    #pragma unroll
    for (int sub = 0; sub < 2; sub++) {
        #pragma unroll
        for (int half = 0; half < 2; half++) {
            int m = mt * 128 + wm * 32 + sub * 16 + g + half * 8;
            #pragma unroll
            for (int nt = 0; nt < 4; nt++) {
                int n = nt0 * 64 + wn * 32 + nt * 8 + 2 * tg;
                float v0 = c[sub][nt][half * 2 + 0] + bo[n];
                float v1 = c[sub][nt][half * 2 + 1] + bo[n + 1];
                *(float2*)&out[(size_t)m * D_ + n] = make_float2(v0, v1);
            }
        }
    }
}

// ---------------------------------------------------------------------------
// Flash attention with tf32 mma. Block: 128 q-rows, one (head, batch, q-tile).
// 8 warps; warp w owns q-rows 16w..16w+15 across the whole kernel.
// smem floats: Ks 2x[64][68], Vs 2x[64][72], Ps [128][68]
// ---------------------------------------------------------------------------
#define KS_STRIDE 68
#define VS_STRIDE 72
#define KS_BUF (64*KS_STRIDE)
#define VS_BUF (64*VS_STRIDE)
#define PS_OFF  (2*KS_BUF + 2*VS_BUF)
#define ATTN_SMEM ((PS_OFF + 128*KS_STRIDE) * 4)   // 106496 B

__device__ __forceinline__ void attn_stage(const float* __restrict__ Kg,
                                           const float* __restrict__ Vg,
                                           uint32_t ks_b, uint32_t vs_b,
                                           int kt, int buf, int tid)
{
    const float* ksrc = Kg + (size_t)kt * 64 * DH_;
    const float* vsrc = Vg + (size_t)kt * 64 * DH_;
    uint32_t kb = ks_b + buf * (KS_BUF * 4);
    uint32_t vb = vs_b + buf * (VS_BUF * 4);
    #pragma unroll
    for (int t = 0; t < 4; t++) {
        int idx = tid + t * 256;
        int r = idx >> 4, c4 = (idx & 15) * 4;
        cp16(kb + (r * KS_STRIDE + c4) * 4, ksrc + r * DH_ + c4);
        cp16(vb + (r * VS_STRIDE + c4) * 4, vsrc + r * DH_ + c4);
    }
}

__global__ __launch_bounds__(256) void attn_kernel()
{
    extern __shared__ float sm[];
    float* Ks = sm;
    float* Vs = sm + 2 * KS_BUF;
    float* Ps = sm + PS_OFF;

    const int tid = threadIdx.x;
    const int wid = tid >> 5, lane = tid & 31;
    const int g = lane >> 2, tg = lane & 3;
    const int qt = blockIdx.x, h = blockIdx.y, b = blockIdx.z;
    const int bh = b * H_ + h;
    const int r0 = wid * 16 + g;      // block-local q row (and r0+8)

    uint32_t ks_b = smem_u32(Ks), vs_b = smem_u32(Vs);

    // Q fragments in registers for the whole kernel (g_Q pre-scaled + rounded)
    const float* Qg = g_Q + ((size_t)bh * S_ + qt * 128) * DH_;
    uint32_t qf[8][4];
    #pragma unroll
    for (int ks = 0; ks < 8; ks++) {
        int col = ks * 8 + tg;
        qf[ks][0] = fu(Qg[r0 * DH_ + col]);
        qf[ks][1] = fu(Qg[(r0 + 8) * DH_ + col]);
        qf[ks][2] = fu(Qg[r0 * DH_ + col + 4]);
        qf[ks][3] = fu(Qg[(r0 + 8) * DH_ + col + 4]);
    }

    float oc[8][4];
    #pragma unroll
    for (int nt = 0; nt < 8; nt++)
        #pragma unroll
        for (int q = 0; q < 4; q++) oc[nt][q] = 0.f;
    float m0 = -1e30f, m1 = -1e30f, l0 = 0.f, l1 = 0.f;

    const float* Kg = g_K + (size_t)bh * S_ * DH_;
    const float* Vg = g_V + (size_t)bh * S_ * DH_;

    attn_stage(Kg, Vg, ks_b, vs_b, 0, 0, tid);
    CP_COMMIT();

    for (int kt = 0; kt < 32; kt++) {
        int p = kt & 1;
        if (kt + 1 < 32) {
            __syncthreads();
            attn_stage(Kg, Vg, ks_b, vs_b, kt + 1, !p, tid);
            CP_COMMIT();
            CP_WAIT(1);
        } else {
            CP_WAIT(0);
        }
        __syncthreads();

        const float* Kb = Ks + p * KS_BUF;
        const float* Vb = Vs + p * VS_BUF;

        // S = Q @ K^T  (n = key within tile, k = dh)
        float sc[8][4];
        #pragma unroll
        for (int nt = 0; nt < 8; nt++)
            #pragma unroll
            for (int q = 0; q < 4; q++) sc[nt][q] = 0.f;

        #pragma unroll
        for (int ks = 0; ks < 8; ks++) {
            int col = ks * 8 + tg;
            #pragma unroll
            for (int nt = 0; nt < 8; nt++) {
                const float* krow = Kb + (nt * 8 + g) * KS_STRIDE;
                mma8(sc[nt], qf[ks][0], qf[ks][1], qf[ks][2], qf[ks][3],
                     fu(krow[col]), fu(krow[col + 4]));
            }
        }

        // online softmax (rows r0 and r0+8; quad lanes share a row)
        float mx0 = -1e30f, mx1 = -1e30f;
        #pragma unroll
        for (int nt = 0; nt < 8; nt++) {
            mx0 = fmaxf(mx0, fmaxf(sc[nt][0], sc[nt][1]));
            mx1 = fmaxf(mx1, fmaxf(sc[nt][2], sc[nt][3]));
        }
        mx0 = fmaxf(mx0, __shfl_xor_sync(0xffffffffu, mx0, 1));
        mx0 = fmaxf(mx0, __shfl_xor_sync(0xffffffffu, mx0, 2));
        mx1 = fmaxf(mx1, __shfl_xor_sync(0xffffffffu, mx1, 1));
        mx1 = fmaxf(mx1, __shfl_xor_sync(0xffffffffu, mx1, 2));

        float mn0 = fmaxf(m0, mx0), mn1 = fmaxf(m1, mx1);
        float corr0 = __expf(m0 - mn0), corr1 = __expf(m1 - mn1);
        float sum0 = 0.f, sum1 = 0.f;
        #pragma unroll
        for (int nt = 0; nt < 8; nt++) {
            sc[nt][0] = __expf(sc[nt][0] - mn0);
            sc[nt][1] = __expf(sc[nt][1] - mn0);
            sc[nt][2] = __expf(sc[nt][2] - mn1);
            sc[nt][3] = __expf(sc[nt][3] - mn1);
            sum0 += sc[nt][0] + sc[nt][1];
            sum1 += sc[nt][2] + sc[nt][3];
        }
        sum0 += __shfl_xor_sync(0xffffffffu, sum0, 1);
        sum0 += __shfl_xor_sync(0xffffffffu, sum0, 2);
        sum1 += __shfl_xor_sync(0xffffffffu, sum1, 1);
        sum1 += __shfl_xor_sync(0xffffffffu, sum1, 2);
        l0 = l0 * corr0 + sum0;  m0 = mn0;
        l1 = l1 * corr1 + sum1;  m1 = mn1;
        #pragma unroll
        for (int nt = 0; nt < 8; nt++) {
            oc[nt][0] *= corr0; oc[nt][1] *= corr0;
            oc[nt][2] *= corr1; oc[nt][3] *= corr1;
        }

        // store P (tf32-rounded); per-warp private rows -> __syncwarp only
        #pragma unroll
        for (int nt = 0; nt < 8; nt++) {
            int cidx = nt * 8 + 2 * tg;
            *(float2*)&Ps[r0 * KS_STRIDE + cidx] =
                make_float2(rna(sc[nt][0]), rna(sc[nt][1]));
            *(float2*)&Ps[(r0 + 8) * KS_STRIDE + cidx] =
                make_float2(rna(sc[nt][2]), rna(sc[nt][3]));
        }
        __syncwarp();

        // O += P @ V  (k = key within tile, n = dh)
        #pragma unroll
        for (int ks = 0; ks < 8; ks++) {
            int col = ks * 8 + tg;
            uint32_t a0 = fu(Ps[r0 * KS_STRIDE + col]);
            uint32_t a1 = fu(Ps[(r0 + 8) * KS_STRIDE + col]);
            uint32_t a2 = fu(Ps[r0 * KS_STRIDE + col + 4]);
            uint32_t a3 = fu(Ps[(r0 + 8) * KS_STRIDE + col + 4]);
            #pragma unroll
            for (int nt = 0; nt < 8; nt++) {
                uint32_t b0 = fu(Vb[(ks * 8 + tg) * VS_STRIDE + nt * 8 + g]);
                uint32_t b1 = fu(Vb[(ks * 8 + tg + 4) * VS_STRIDE + nt * 8 + g]);
                mma8(oc[nt], a0, a1, a2, a3, b0, b1);
            }
        }
    }

    // epilogue: normalize, round, store ctx in concat layout
    float inv0 = 1.f / l0, inv1 = 1.f / l1;
    int s0 = qt * 128 + r0;
    float* row0 = g_C + ((size_t)b * S_ + s0) * D_ + h * DH_;
    float* row1 = row0 + 8 * D_;
    #pragma unroll
    for (int nt = 0; nt < 8; nt++) {
        int cidx = nt * 8 + 2 * tg;
        *(float2*)&row0[cidx] =
            make_float2(rna(oc[nt][0] * inv0), rna(oc[nt][1] * inv0));
        *(float2*)&row1[cidx] =
            make_float2(rna(oc[nt][2] * inv1), rna(oc[nt][3] * inv1));
    }
}

// ---------------------------------------------------------------------------
extern "C" void kernel_launch(void* const* d_in, const int* in_sizes, int n_in,
                              void* d_out, int out_size)
{
    const float* x  = (const float*)d_in[0];
    const float* Wq = (const float*)d_in[1];
    const float* bq = (const float*)d_in[2];
    const float* Wk = (const float*)d_in[3];
    const float* bk = (const float*)d_in[4];
    const float* Wv = (const float*)d_in[5];
    const float* bv = (const float*)d_in[6];
    const float* Wo = (const float*)d_in[7];
    const float* bo = (const float*)d_in[8];
    float* out = (float*)d_out;

    cudaFuncSetAttribute(attn_kernel,
                         cudaFuncAttributeMaxDynamicSharedMemorySize, ATTN_SMEM);
    cudaFuncSetAttribute(qkv_gemm_kernel,
                         cudaFuncAttributeMaxDynamicSharedMemorySize, GEMM_SMEM);
    cudaFuncSetAttribute(proj_gemm_kernel,
                         cudaFuncAttributeMaxDynamicSharedMemorySize, GEMM_SMEM);

    cvt_x_kernel<<<B_ * S_ * D_ / (256 * 4), 256>>>(x);
    transpose_qkv_kernel<<<dim3(32, 2, 48), 256>>>(Wq, Wk, Wv);
    transpose_wo_kernel<<<dim3(32, 32), 256>>>(Wo);
    qkv_gemm_kernel<<<dim3(64, 48), 256, GEMM_SMEM>>>(bq, bk, bv);
    attn_kernel<<<dim3(16, 16, 4), 256, ATTN_SMEM>>>();
    proj_gemm_kernel<<<dim3(64, 16), 256, GEMM_SMEM>>>(bo, out);
}

// round 4
// speedup vs baseline: 3.2351x; 1.0700x over previous
#include <cuda_runtime.h>
#include <cstdint>
#include <math.h>

#define B_  4
#define S_  2048
#define D_  1024
#define H_  16
#define DH_ 64

// ---------------------------------------------------------------------------
// Scratch (__device__ globals; no runtime allocation allowed)
// ---------------------------------------------------------------------------
__device__ float g_X  [B_*S_*D_];          // tf32-rounded x
__device__ float g_Q  [B_*H_*S_*DH_];      // [B,H,S,DH]  (pre-scaled by 0.125, rounded)
__device__ float g_K  [B_*H_*S_*DH_];      // [B,H,S,DH]  (rounded)
__device__ float g_V  [B_*H_*S_*DH_];      // [B,H,S,DH]  (rounded)
__device__ float g_C  [B_*S_*D_];          // [B,S,D] concat ctx (rounded)
__device__ float g_Wt [48*DH_*D_];         // row n=z*64+e over [1024] (rounded)
__device__ float g_WoT[D_*D_];             // [n][k] = Wo[k][n]        (rounded)

// ---------------------------------------------------------------------------
// Helpers
// ---------------------------------------------------------------------------
__device__ __forceinline__ uint32_t smem_u32(const void* p) {
    uint32_t a;
    asm("{ .reg .u64 t; cvta.to.shared.u64 t, %1; cvt.u32.u64 %0, t; }" : "=r"(a) : "l"(p));
    return a;
}
__device__ __forceinline__ float rna(float f) {
    uint32_t u;
    asm("cvt.rna.tf32.f32 %0, %1;" : "=r"(u) : "f"(f));
    return __uint_as_float(u);
}
__device__ __forceinline__ void cp16(uint32_t sa, const void* g) {
    asm volatile("cp.async.cg.shared.global [%0], [%1], 16;" :: "r"(sa), "l"(g));
}
#define CP_COMMIT() asm volatile("cp.async.commit_group;" ::: "memory")
#define CP_WAIT(n)  asm volatile("cp.async.wait_group %0;" :: "n"(n) : "memory")

// D(16x8) += A(16x8) * B(8x8), tf32 inputs, f32 accum.
__device__ __forceinline__ void mma8(float* c, uint32_t a0, uint32_t a1, uint32_t a2,
                                     uint32_t a3, uint32_t b0, uint32_t b1) {
    asm volatile(
        "mma.sync.aligned.m16n8k8.row.col.f32.tf32.tf32.f32 "
        "{%0,%1,%2,%3}, {%4,%5,%6,%7}, {%8,%9}, {%0,%1,%2,%3};"
        : "+f"(c[0]), "+f"(c[1]), "+f"(c[2]), "+f"(c[3])
        : "r"(a0), "r"(a1), "r"(a2), "r"(a3), "r"(b0), "r"(b1));
}
__device__ __forceinline__ uint32_t fu(float f) { return __float_as_uint(f); }

// ---------------------------------------------------------------------------
// Prep kernels
// ---------------------------------------------------------------------------
__global__ __launch_bounds__(256) void cvt_x_kernel(const float* __restrict__ x)
{
    int i = (blockIdx.x * 256 + threadIdx.x) * 4;
    float4 v = *(const float4*)&x[i];
    v.x = rna(v.x); v.y = rna(v.y); v.z = rna(v.z); v.w = rna(v.w);
    *(float4*)&g_X[i] = v;
}

__global__ __launch_bounds__(256) void transpose_qkv_kernel(
    const float* __restrict__ Wq, const float* __restrict__ Wk, const float* __restrict__ Wv)
{
    __shared__ float t[32][33];
    int z = blockIdx.z;            // 0..47 = h*3 + mtx
    int h = z / 3, mtx = z % 3;
    const float* W = (mtx == 0 ? Wq : (mtx == 1 ? Wk : Wv)) + h * D_ * DH_;
    float* out = g_Wt + (size_t)z * DH_ * D_;
    int d0 = blockIdx.x * 32, e0 = blockIdx.y * 32;
    int tx = threadIdx.x & 31, ty = threadIdx.x >> 5;
    #pragma unroll
    for (int i = 0; i < 4; i++)
        t[ty + 8 * i][tx] = W[(d0 + ty + 8 * i) * DH_ + e0 + tx];
    __syncthreads();
    #pragma unroll
    for (int i = 0; i < 4; i++)
        out[(e0 + ty + 8 * i) * D_ + d0 + tx] = rna(t[tx][ty + 8 * i]);
}

__global__ __launch_bounds__(256) void transpose_wo_kernel(const float* __restrict__ Wo)
{
    __shared__ float t[32][33];
    int d0 = blockIdx.x * 32, n0 = blockIdx.y * 32;
    int tx = threadIdx.x & 31, ty = threadIdx.x >> 5;
    #pragma unroll
    for (int i = 0; i < 4; i++)
        t[ty + 8 * i][tx] = Wo[(d0 + ty + 8 * i) * D_ + n0 + tx];
    __syncthreads();
    #pragma unroll
    for (int i = 0; i < 4; i++)
        g_WoT[(n0 + ty + 8 * i) * D_ + d0 + tx] = rna(t[tx][ty + 8 * i]);
}

// ---------------------------------------------------------------------------
// 128x128x1024 GEMM mainloop (tf32 mma). 256 threads = warps 4(m) x 2(n),
// warp tile 32x64. smem: As 2x[128][36], Bs 2x[128][36] = 73728 B.
// ---------------------------------------------------------------------------
#define TS 36
#define TBUF (128*TS)
#define GEMM_SMEM (4 * TBUF * 4)

__device__ __forceinline__ void gemm_stage(const float* __restrict__ Ag,
                                           const float* __restrict__ Bg,
                                           uint32_t as_b, uint32_t bs_b,
                                           int k0, int buf, int tid)
{
    uint32_t ab = as_b + buf * (TBUF * 4);
    uint32_t bb = bs_b + buf * (TBUF * 4);
    #pragma unroll
    for (int t = 0; t < 4; t++) {
        int idx = tid + t * 256;
        int r = idx >> 3, c4 = (idx & 7) * 4;
        cp16(ab + (r * TS + c4) * 4, Ag + (size_t)r * D_ + k0 + c4);
        cp16(bb + (r * TS + c4) * 4, Bg + (size_t)r * D_ + k0 + c4);
    }
}

__device__ __forceinline__ void gemm_mainloop(const float* __restrict__ Ag,
                                              const float* __restrict__ Bg,
                                              float c[2][8][4], float* sm)
{
    float* As = sm;
    float* Bs = sm + 2 * TBUF;
    const int tid = threadIdx.x;
    const int wid = tid >> 5, lane = tid & 31;
    const int g = lane >> 2, tg = lane & 3;
    const int wm = wid >> 1, wn = wid & 1;
    uint32_t as_b = smem_u32(As), bs_b = smem_u32(Bs);

    #pragma unroll
    for (int i = 0; i < 2; i++)
        #pragma unroll
        for (int j = 0; j < 8; j++)
            #pragma unroll
            for (int q = 0; q < 4; q++) c[i][j][q] = 0.f;

    gemm_stage(Ag, Bg, as_b, bs_b, 0, 0, tid);
    CP_COMMIT();

    for (int s = 0; s < 32; s++) {
        int p = s & 1;
        if (s + 1 < 32) {
            __syncthreads();
            gemm_stage(Ag, Bg, as_b, bs_b, (s + 1) * 32, !p, tid);
            CP_COMMIT();
            CP_WAIT(1);
        } else {
            CP_WAIT(0);
        }
        __syncthreads();

        const float* Ab = As + p * TBUF;
        const float* Bb = Bs + p * TBUF;
        #pragma unroll
        for (int ks = 0; ks < 4; ks++) {
            int col = ks * 8 + tg;
            uint32_t a[2][4], b[8][2];
            #pragma unroll
            for (int sub = 0; sub < 2; sub++) {
                int r = wm * 32 + sub * 16 + g;
                a[sub][0] = fu(Ab[r * TS + col]);
                a[sub][1] = fu(Ab[(r + 8) * TS + col]);
                a[sub][2] = fu(Ab[r * TS + col + 4]);
                a[sub][3] = fu(Ab[(r + 8) * TS + col + 4]);
            }
            #pragma unroll
            for (int nt = 0; nt < 8; nt++) {
                int r = wn * 64 + nt * 8 + g;
                b[nt][0] = fu(Bb[r * TS + col]);
                b[nt][1] = fu(Bb[r * TS + col + 4]);
            }
            #pragma unroll
            for (int sub = 0; sub < 2; sub++)
                #pragma unroll
                for (int nt = 0; nt < 8; nt++)
                    mma8(c[sub][nt], a[sub][0], a[sub][1], a[sub][2], a[sub][3],
                         b[nt][0], b[nt][1]);
        }
    }
}

// ---------------------------------------------------------------------------
// QKV GEMM: [8192,1024] @ g_Wt[3072,1024]^T. grid (64, 24).
// Each warp's 64-col span = exactly one z = bn*2 + wn.
// ---------------------------------------------------------------------------
__global__ __launch_bounds__(256, 2) void qkv_gemm_kernel(
    const float* __restrict__ bq, const float* __restrict__ bk,
    const float* __restrict__ bv)
{
    extern __shared__ float sm[];
    const int mt = blockIdx.x, bn = blockIdx.y;
    float c[2][8][4];
    gemm_mainloop(g_X + (size_t)mt * 128 * D_,
                  g_Wt + (size_t)bn * 128 * D_, c, sm);

    const int tid = threadIdx.x;
    const int wid = tid >> 5, lane = tid & 31;
    const int g = lane >> 2, tg = lane & 3;
    const int wm = wid >> 1, wn = wid & 1;

    const int z = bn * 2 + wn;
    const int h = z / 3, mtx = z % 3;
    const float* bias = (mtx == 0 ? bq : (mtx == 1 ? bk : bv)) + h * DH_;
    float* dst = (mtx == 0 ? g_Q : (mtx == 1 ? g_K : g_V));
    const float scale = (mtx == 0) ? 0.125f : 1.0f;

    #pragma unroll
    for (int sub = 0; sub < 2; sub++) {
        #pragma unroll
        for (int half = 0; half < 2; half++) {
            int m = mt * 128 + wm * 32 + sub * 16 + g + half * 8;
            int bi = m >> 11, si = m & 2047;
            float* row = dst + ((size_t)(bi * H_ + h) * S_ + si) * DH_;
            #pragma unroll
            for (int nt = 0; nt < 8; nt++) {
                int e = nt * 8 + 2 * tg;
                float v0 = rna((c[sub][nt][half * 2 + 0] + bias[e]) * scale);
                float v1 = rna((c[sub][nt][half * 2 + 1] + bias[e + 1]) * scale);
                *(float2*)&row[e] = make_float2(v0, v1);
            }
        }
    }
}

// ---------------------------------------------------------------------------
// Output projection GEMM: grid (64, 8)
// ---------------------------------------------------------------------------
__global__ __launch_bounds__(256, 2) void proj_gemm_kernel(
    const float* __restrict__ bo, float* __restrict__ out)
{
    extern __shared__ float sm[];
    const int mt = blockIdx.x, bn = blockIdx.y;
    float c[2][8][4];
    gemm_mainloop(g_C + (size_t)mt * 128 * D_,
                  g_WoT + (size_t)bn * 128 * D_, c, sm);

    const int tid = threadIdx.x;
    const int wid = tid >> 5, lane = tid & 31;
    const int g = lane >> 2, tg = lane & 3;
    const int wm = wid >> 1, wn = wid & 1;

    #pragma unroll
    for (int sub = 0; sub < 2; sub++) {
        #pragma unroll
        for (int half = 0; half < 2; half++) {
            int m = mt * 128 + wm * 32 + sub * 16 + g + half * 8;
            #pragma unroll
            for (int nt = 0; nt < 8; nt++) {
                int n = bn * 128 + wn * 64 + nt * 8 + 2 * tg;
                float v0 = c[sub][nt][half * 2 + 0] + bo[n];
                float v1 = c[sub][nt][half * 2 + 1] + bo[n + 1];
                *(float2*)&out[(size_t)m * D_ + n] = make_float2(v0, v1);
            }
        }
    }
}

// ---------------------------------------------------------------------------
// Flash attention with tf32 mma (structure from round 3; now 2 CTAs/SM)
// ---------------------------------------------------------------------------
#define KS_STRIDE 68
#define VS_STRIDE 72
#define KS_BUF (64*KS_STRIDE)
#define VS_BUF (64*VS_STRIDE)
#define PS_OFF  (2*KS_BUF + 2*VS_BUF)
#define ATTN_SMEM ((PS_OFF + 128*KS_STRIDE) * 4)   // 106496 B

__device__ __forceinline__ void attn_stage(const float* __restrict__ Kg,
                                           const float* __restrict__ Vg,
                                           uint32_t ks_b, uint32_t vs_b,
                                           int kt, int buf, int tid)
{
    const float* ksrc = Kg + (size_t)kt * 64 * DH_;
    const float* vsrc = Vg + (size_t)kt * 64 * DH_;
    uint32_t kb = ks_b + buf * (KS_BUF * 4);
    uint32_t vb = vs_b + buf * (VS_BUF * 4);
    #pragma unroll
    for (int t = 0; t < 4; t++) {
        int idx = tid + t * 256;
        int r = idx >> 4, c4 = (idx & 15) * 4;
        cp16(kb + (r * KS_STRIDE + c4) * 4, ksrc + r * DH_ + c4);
        cp16(vb + (r * VS_STRIDE + c4) * 4, vsrc + r * DH_ + c4);
    }
}

__global__ __launch_bounds__(256, 2) void attn_kernel()
{
    extern __shared__ float sm[];
    float* Ks = sm;
    float* Vs = sm + 2 * KS_BUF;
    float* Ps = sm + PS_OFF;

    const int tid = threadIdx.x;
    const int wid = tid >> 5, lane = tid & 31;
    const int g = lane >> 2, tg = lane & 3;
    const int qt = blockIdx.x, h = blockIdx.y, b = blockIdx.z;
    const int bh = b * H_ + h;
    const int r0 = wid * 16 + g;

    uint32_t ks_b = smem_u32(Ks), vs_b = smem_u32(Vs);

    const float* Qg = g_Q + ((size_t)bh * S_ + qt * 128) * DH_;
    uint32_t qf[8][4];
    #pragma unroll
    for (int ks = 0; ks < 8; ks++) {
        int col = ks * 8 + tg;
        qf[ks][0] = fu(Qg[r0 * DH_ + col]);
        qf[ks][1] = fu(Qg[(r0 + 8) * DH_ + col]);
        qf[ks][2] = fu(Qg[r0 * DH_ + col + 4]);
        qf[ks][3] = fu(Qg[(r0 + 8) * DH_ + col + 4]);
    }

    float oc[8][4];
    #pragma unroll
    for (int nt = 0; nt < 8; nt++)
        #pragma unroll
        for (int q = 0; q < 4; q++) oc[nt][q] = 0.f;
    float m0 = -1e30f, m1 = -1e30f, l0 = 0.f, l1 = 0.f;

    const float* Kg = g_K + (size_t)bh * S_ * DH_;
    const float* Vg = g_V + (size_t)bh * S_ * DH_;

    attn_stage(Kg, Vg, ks_b, vs_b, 0, 0, tid);
    CP_COMMIT();

    for (int kt = 0; kt < 32; kt++) {
        int p = kt & 1;
        if (kt + 1 < 32) {
            __syncthreads();
            attn_stage(Kg, Vg, ks_b, vs_b, kt + 1, !p, tid);
            CP_COMMIT();
            CP_WAIT(1);
        } else {
            CP_WAIT(0);
        }
        __syncthreads();

        const float* Kb = Ks + p * KS_BUF;
        const float* Vb = Vs + p * VS_BUF;

        float sc[8][4];
        #pragma unroll
        for (int nt = 0; nt < 8; nt++)
            #pragma unroll
            for (int q = 0; q < 4; q++) sc[nt][q] = 0.f;

        #pragma unroll
        for (int ks = 0; ks < 8; ks++) {
            int col = ks * 8 + tg;
            #pragma unroll
            for (int nt = 0; nt < 8; nt++) {
                const float* krow = Kb + (nt * 8 + g) * KS_STRIDE;
                mma8(sc[nt], qf[ks][0], qf[ks][1], qf[ks][2], qf[ks][3],
                     fu(krow[col]), fu(krow[col + 4]));
            }
        }

        float mx0 = -1e30f, mx1 = -1e30f;
        #pragma unroll
        for (int nt = 0; nt < 8; nt++) {
            mx0 = fmaxf(mx0, fmaxf(sc[nt][0], sc[nt][1]));
            mx1 = fmaxf(mx1, fmaxf(sc[nt][2], sc[nt][3]));
        }
        mx0 = fmaxf(mx0, __shfl_xor_sync(0xffffffffu, mx0, 1));
        mx0 = fmaxf(mx0, __shfl_xor_sync(0xffffffffu, mx0, 2));
        mx1 = fmaxf(mx1, __shfl_xor_sync(0xffffffffu, mx1, 1));
        mx1 = fmaxf(mx1, __shfl_xor_sync(0xffffffffu, mx1, 2));

        float mn0 = fmaxf(m0, mx0), mn1 = fmaxf(m1, mx1);
        float corr0 = __expf(m0 - mn0), corr1 = __expf(m1 - mn1);
        float sum0 = 0.f, sum1 = 0.f;
        #pragma unroll
        for (int nt = 0; nt < 8; nt++) {
            sc[nt][0] = __expf(sc[nt][0] - mn0);
            sc[nt][1] = __expf(sc[nt][1] - mn0);
            sc[nt][2] = __expf(sc[nt][2] - mn1);
            sc[nt][3] = __expf(sc[nt][3] - mn1);
            sum0 += sc[nt][0] + sc[nt][1];
            sum1 += sc[nt][2] + sc[nt][3];
        }
        sum0 += __shfl_xor_sync(0xffffffffu, sum0, 1);
        sum0 += __shfl_xor_sync(0xffffffffu, sum0, 2);
        sum1 += __shfl_xor_sync(0xffffffffu, sum1, 1);
        sum1 += __shfl_xor_sync(0xffffffffu, sum1, 2);
        l0 = l0 * corr0 + sum0;  m0 = mn0;
        l1 = l1 * corr1 + sum1;  m1 = mn1;
        #pragma unroll
        for (int nt = 0; nt < 8; nt++) {
            oc[nt][0] *= corr0; oc[nt][1] *= corr0;
            oc[nt][2] *= corr1; oc[nt][3] *= corr1;
        }

        #pragma unroll
        for (int nt = 0; nt < 8; nt++) {
            int cidx = nt * 8 + 2 * tg;
            *(float2*)&Ps[r0 * KS_STRIDE + cidx] =
                make_float2(rna(sc[nt][0]), rna(sc[nt][1]));
            *(float2*)&Ps[(r0 + 8) * KS_STRIDE + cidx] =
                make_float2(rna(sc[nt][2]), rna(sc[nt][3]));
        }
        __syncwarp();

        #pragma unroll
        for (int ks = 0; ks < 8; ks++) {
            int col = ks * 8 + tg;
            uint32_t a0 = fu(Ps[r0 * KS_STRIDE + col]);
            uint32_t a1 = fu(Ps[(r0 + 8) * KS_STRIDE + col]);
            uint32_t a2 = fu(Ps[r0 * KS_STRIDE + col + 4]);
            uint32_t a3 = fu(Ps[(r0 + 8) * KS_STRIDE + col + 4]);
            #pragma unroll
            for (int nt = 0; nt < 8; nt++) {
                uint32_t b0 = fu(Vb[(ks * 8 + tg) * VS_STRIDE + nt * 8 + g]);
                uint32_t b1 = fu(Vb[(ks * 8 + tg + 4) * VS_STRIDE + nt * 8 + g]);
                mma8(oc[nt], a0, a1, a2, a3, b0, b1);
            }
        }
    }

    float inv0 = 1.f / l0, inv1 = 1.f / l1;
    int s0 = qt * 128 + r0;
    float* row0 = g_C + ((size_t)b * S_ + s0) * D_ + h * DH_;
    float* row1 = row0 + 8 * D_;
    #pragma unroll
    for (int nt = 0; nt < 8; nt++) {
        int cidx = nt * 8 + 2 * tg;
        *(float2*)&row0[cidx] =
            make_float2(rna(oc[nt][0] * inv0), rna(oc[nt][1] * inv0));
        *(float2*)&row1[cidx] =
            make_float2(rna(oc[nt][2] * inv1), rna(oc[nt][3] * inv1));
    }
}

// ---------------------------------------------------------------------------
extern "C" void kernel_launch(void* const* d_in, const int* in_sizes, int n_in,
                              void* d_out, int out_size)
{
    const float* x  = (const float*)d_in[0];
    const float* Wq = (const float*)d_in[1];
    const float* bq = (const float*)d_in[2];
    const float* Wk = (const float*)d_in[3];
    const float* bk = (const float*)d_in[4];
    const float* Wv = (const float*)d_in[5];
    const float* bv = (const float*)d_in[6];
    const float* Wo = (const float*)d_in[7];
    const float* bo = (const float*)d_in[8];
    float* out = (float*)d_out;

    cudaFuncSetAttribute(attn_kernel,
                         cudaFuncAttributeMaxDynamicSharedMemorySize, ATTN_SMEM);
    cudaFuncSetAttribute(qkv_gemm_kernel,
                         cudaFuncAttributeMaxDynamicSharedMemorySize, GEMM_SMEM);
    cudaFuncSetAttribute(proj_gemm_kernel,
                         cudaFuncAttributeMaxDynamicSharedMemorySize, GEMM_SMEM);

    cvt_x_kernel<<<B_ * S_ * D_ / (256 * 4), 256>>>(x);
    transpose_qkv_kernel<<<dim3(32, 2, 48), 256>>>(Wq, Wk, Wv);
    transpose_wo_kernel<<<dim3(32, 32), 256>>>(Wo);
    qkv_gemm_kernel<<<dim3(64, 24), 256, GEMM_SMEM>>>(bq, bk, bv);
    attn_kernel<<<dim3(16, 16, 4), 256, ATTN_SMEM>>>();
    proj_gemm_kernel<<<dim3(64, 8), 256, GEMM_SMEM>>>(bo, out);
}